// round 2
// baseline (speedup 1.0000x reference)
#include <cuda_runtime.h>
#include <math.h>

#define MATN 4096
#define NSQL ((size_t)MATN * (size_t)MATN)

// Static device scratch (allowed; no runtime allocation).
__device__ float g_X0[MATN * MATN];
__device__ float g_X1[MATN * MATN];
__device__ float g_S [MATN * MATN];
__device__ float g_P [MATN * MATN];
__device__ float g_part[256];
__device__ float g_scal[4];   // [0] = ||H||_F^2

// ---------------- reduction helpers ----------------

__global__ void k_sumsq(const float* __restrict__ x, int n, float* __restrict__ part) {
    __shared__ float sm[256];
    float acc = 0.f;
    for (int i = blockIdx.x * blockDim.x + threadIdx.x; i < n; i += gridDim.x * blockDim.x) {
        float v = x[i];
        acc = fmaf(v, v, acc);
    }
    sm[threadIdx.x] = acc; __syncthreads();
    for (int s = 128; s > 0; s >>= 1) {
        if (threadIdx.x < s) sm[threadIdx.x] += sm[threadIdx.x + s];
        __syncthreads();
    }
    if (threadIdx.x == 0) part[blockIdx.x] = sm[0];
}

__global__ void k_finish(const float* __restrict__ part, float* __restrict__ dst) {
    __shared__ float sm[256];
    sm[threadIdx.x] = part[threadIdx.x]; __syncthreads();
    for (int s = 128; s > 0; s >>= 1) {
        if (threadIdx.x < s) sm[threadIdx.x] += sm[threadIdx.x + s];
        __syncthreads();
    }
    if (threadIdx.x == 0) *dst = sm[0];
}

// X = H * (1/||H||_F)
__global__ void k_scalemat(const float* __restrict__ H, float* __restrict__ X,
                           const float* __restrict__ scal) {
    float s = rsqrtf(scal[0] + 1e-30f);
    for (size_t i = (size_t)blockIdx.x * blockDim.x + threadIdx.x; i < NSQL;
         i += (size_t)gridDim.x * blockDim.x)
        X[i] = H[i] * s;
}

// ---------------- SGEMM: C = op(A)*B (+ optional quintic epilogue) ----------------
// TRANSA=1: C = A^T * B               (S = X^T X)
// POLY=1:   C = c2*(A*B) + c1*E + c0*I   (P = c0 I + c1 S + c2 S^2, E = S)

#define BM 128
#define BN 128
#define BK 16

template<int TRANSA, int POLY>
__global__ void __launch_bounds__(256, 2)
sgemm_k(const float* __restrict__ Ag, const float* __restrict__ Bg,
        float* __restrict__ Cg, const float* __restrict__ Eg,
        float c0, float c1, float c2)
{
    __shared__ float As[2][BK][BM];
    __shared__ float Bs[2][BK][BN];

    const int tid  = threadIdx.x;
    const int tx   = tid & 15;          // 0..15 -> column groups of 8
    const int ty   = tid >> 4;          // 0..15 -> row groups of 8
    const int row0 = blockIdx.y * BM;
    const int col0 = blockIdx.x * BN;

    float acc[8][8];
    #pragma unroll
    for (int i = 0; i < 8; ++i)
        #pragma unroll
        for (int j = 0; j < 8; ++j) acc[i][j] = 0.f;

    float4 ra[2], rb[2];

    auto fetchA = [&](int kt) {
        if (TRANSA) {
            #pragma unroll
            for (int h = 0; h < 2; ++h) {
                int q = tid + h * 256;
                int kr = q >> 5, cc = (q & 31) << 2;
                ra[h] = *reinterpret_cast<const float4*>(
                    Ag + (size_t)(kt * BK + kr) * MATN + row0 + cc);
            }
        } else {
            #pragma unroll
            for (int h = 0; h < 2; ++h) {
                int q = tid + h * 256;
                int rr = q >> 2, kq = (q & 3) << 2;
                ra[h] = *reinterpret_cast<const float4*>(
                    Ag + (size_t)(row0 + rr) * MATN + kt * BK + kq);
            }
        }
    };
    auto storeA = [&](int buf) {
        if (TRANSA) {
            #pragma unroll
            for (int h = 0; h < 2; ++h) {
                int q = tid + h * 256;
                int kr = q >> 5, cc = (q & 31) << 2;
                *reinterpret_cast<float4*>(&As[buf][kr][cc]) = ra[h];
            }
        } else {
            #pragma unroll
            for (int h = 0; h < 2; ++h) {
                int q = tid + h * 256;
                int rr = q >> 2, kq = (q & 3) << 2;
                As[buf][kq + 0][rr] = ra[h].x;
                As[buf][kq + 1][rr] = ra[h].y;
                As[buf][kq + 2][rr] = ra[h].z;
                As[buf][kq + 3][rr] = ra[h].w;
            }
        }
    };
    auto fetchB = [&](int kt) {
        #pragma unroll
        for (int h = 0; h < 2; ++h) {
            int q = tid + h * 256;
            int kr = q >> 5, cc = (q & 31) << 2;
            rb[h] = *reinterpret_cast<const float4*>(
                Bg + (size_t)(kt * BK + kr) * MATN + col0 + cc);
        }
    };
    auto storeB = [&](int buf) {
        #pragma unroll
        for (int h = 0; h < 2; ++h) {
            int q = tid + h * 256;
            int kr = q >> 5, cc = (q & 31) << 2;
            *reinterpret_cast<float4*>(&Bs[buf][kr][cc]) = rb[h];
        }
    };

    fetchA(0); fetchB(0);
    storeA(0); storeB(0);
    __syncthreads();

    const int NT = MATN / BK;
    int cur = 0;
    for (int kt = 0; kt < NT; ++kt) {
        if (kt + 1 < NT) { fetchA(kt + 1); fetchB(kt + 1); }
        #pragma unroll
        for (int kk = 0; kk < BK; ++kk) {
            float a[8], b[8];
            *reinterpret_cast<float4*>(&a[0]) = *reinterpret_cast<const float4*>(&As[cur][kk][ty * 8]);
            *reinterpret_cast<float4*>(&a[4]) = *reinterpret_cast<const float4*>(&As[cur][kk][ty * 8 + 4]);
            *reinterpret_cast<float4*>(&b[0]) = *reinterpret_cast<const float4*>(&Bs[cur][kk][tx * 8]);
            *reinterpret_cast<float4*>(&b[4]) = *reinterpret_cast<const float4*>(&Bs[cur][kk][tx * 8 + 4]);
            #pragma unroll
            for (int i = 0; i < 8; ++i)
                #pragma unroll
                for (int j = 0; j < 8; ++j)
                    acc[i][j] = fmaf(a[i], b[j], acc[i][j]);
        }
        if (kt + 1 < NT) { storeA(cur ^ 1); storeB(cur ^ 1); }
        __syncthreads();
        cur ^= 1;
    }

    #pragma unroll
    for (int i = 0; i < 8; ++i) {
        int r = row0 + ty * 8 + i;
        #pragma unroll
        for (int j4 = 0; j4 < 2; ++j4) {
            int cbase = col0 + tx * 8 + j4 * 4;
            float4 o;
            float* po = &o.x;
            #pragma unroll
            for (int j = 0; j < 4; ++j) {
                float v = acc[i][j4 * 4 + j];
                if (POLY) {
                    int cc = cbase + j;
                    v = c2 * v + c1 * Eg[(size_t)r * MATN + cc] + ((r == cc) ? c0 : 0.f);
                }
                po[j] = v;
            }
            *reinterpret_cast<float4*>(Cg + (size_t)r * MATN + cbase) = o;
        }
    }
}

// ---------------- driver ----------------

extern "C" void kernel_launch(void* const* d_in, const int* in_sizes, int n_in,
                              void* d_out, int out_size)
{
    const float* H = (const float*)d_in[0];
    float* out = (float*)d_out;

    float *X0, *X1, *S, *P, *part, *scal;
    cudaGetSymbolAddress((void**)&X0,   g_X0);
    cudaGetSymbolAddress((void**)&X1,   g_X1);
    cudaGetSymbolAddress((void**)&S,    g_S);
    cudaGetSymbolAddress((void**)&P,    g_P);
    cudaGetSymbolAddress((void**)&part, g_part);
    cudaGetSymbolAddress((void**)&scal, g_scal);

    // 1) Frobenius norm, X0 = H / ||H||_F  (all singular values in (0,1])
    k_sumsq<<<256, 256>>>(H, (int)NSQL, part);
    k_finish<<<1, 256>>>(part, scal);
    k_scalemat<<<2048, 256>>>(H, X0, scal);

    // 2) 16 quintic iterations: 12 lifting + 4 Newton-Schulz
    const int   NSTEP = 16;
    const float LA = 0.998f * 3.9337f,  LB = 0.998f * -10.1084f, LC = 0.998f * 7.1747f;
    const float NA = 15.0f / 8.0f,      NB = -10.0f / 8.0f,      NC = 3.0f / 8.0f;

    dim3 grd(MATN / BN, MATN / BM);
    float* Xc = X0;
    float* Xn = X1;
    for (int st = 0; st < NSTEP; ++st) {
        float a = (st < 12) ? LA : NA;
        float b = (st < 12) ? LB : NB;
        float c = (st < 12) ? LC : NC;
        float* dst = (st == NSTEP - 1) ? out : Xn;

        // S = Xc^T * Xc
        sgemm_k<1, 0><<<grd, 256>>>(Xc, Xc, S, nullptr, 0.f, 0.f, 0.f);
        // P = a*I + b*S + c*S*S
        sgemm_k<0, 1><<<grd, 256>>>(S, S, P, S, a, b, c);
        // Xn = Xc * P
        sgemm_k<0, 0><<<grd, 256>>>(Xc, P, dst, nullptr, 0.f, 0.f, 0.f);

        float* t = Xc; Xc = Xn; Xn = t;
    }
}

// round 5
// speedup vs baseline: 2.7149x; 2.7149x over previous
#include <cuda_runtime.h>
#include <cuda_bf16.h>
#include <cstdint>
#include <math.h>

#define MATN 4096
#define NSQL ((size_t)MATN * (size_t)MATN)

// ---------------- static device scratch ----------------
__device__ float g_X0[MATN * MATN];
__device__ float g_X1[MATN * MATN];
__device__ float g_S [MATN * MATN];
__device__ float g_P [MATN * MATN];
__device__ __nv_bfloat16 g_hA [MATN * MATN];
__device__ __nv_bfloat16 g_lA [MATN * MATN];
__device__ __nv_bfloat16 g_hAT[MATN * MATN];
__device__ __nv_bfloat16 g_lAT[MATN * MATN];
__device__ __nv_bfloat16 g_hS [MATN * MATN];
__device__ __nv_bfloat16 g_lS [MATN * MATN];
__device__ __nv_bfloat16 g_hP [MATN * MATN];
__device__ __nv_bfloat16 g_lP [MATN * MATN];
__device__ float g_part[256];
__device__ float g_scal[4];

// ---------------- helpers ----------------
__device__ __forceinline__ uint32_t smem_u32(const void* p) {
    uint32_t a;
    asm("{ .reg .u64 t; cvta.to.shared.u64 t, %1; cvt.u32.u64 %0, t; }" : "=r"(a) : "l"(p));
    return a;
}
__device__ __forceinline__ void cp16(uint32_t dst, const void* src) {
    asm volatile("cp.async.cg.shared.global [%0], [%1], 16;" :: "r"(dst), "l"(src));
}
#define CP_COMMIT() asm volatile("cp.async.commit_group;" ::: "memory")
#define CP_WAIT(N)  asm volatile("cp.async.wait_group %0;" :: "n"(N) : "memory")

#define LDSM_X4(r, a)                                                           \
    asm volatile("ldmatrix.sync.aligned.m8n8.x4.shared.b16 {%0,%1,%2,%3}, [%4];" \
        : "=r"((r)[0]), "=r"((r)[1]), "=r"((r)[2]), "=r"((r)[3]) : "r"(a))

__device__ __forceinline__ void mma_bf16(float* d, const uint32_t* a,
                                         uint32_t b0, uint32_t b1) {
    asm volatile(
        "mma.sync.aligned.m16n8k16.row.col.f32.bf16.bf16.f32 "
        "{%0,%1,%2,%3}, {%4,%5,%6,%7}, {%8,%9}, {%0,%1,%2,%3};"
        : "+f"(d[0]), "+f"(d[1]), "+f"(d[2]), "+f"(d[3])
        : "r"(a[0]), "r"(a[1]), "r"(a[2]), "r"(a[3]), "r"(b0), "r"(b1));
}

// ---------------- bf16 tensor-core GEMM (mma.sync) ----------------
// C[m][n] = sum over segs s of sum_k A_s[m][k] * B_s[n][k]   (= A_s * B_s^T)
// POLY=1: C = c2*D + c1*E + c0*I
// Tile: BM=128, BN=128, BK=32. 256 thr (8 warps: 4 row x 2 col, 32x64 each).

#define BROW 80
#define ABYTES (128 * BROW)            // 10240
#define BUFBYTES (2 * ABYTES)

template<int POLY>
__global__ void __launch_bounds__(256, 2)
mma_gemm(const __nv_bfloat16* __restrict__ A0, const __nv_bfloat16* __restrict__ B0,
         const __nv_bfloat16* __restrict__ A1, const __nv_bfloat16* __restrict__ B1,
         const __nv_bfloat16* __restrict__ A2, const __nv_bfloat16* __restrict__ B2,
         int nseg, float* __restrict__ C, const float* __restrict__ E,
         float c0, float c1, float c2)
{
    __shared__ __align__(16) char smem[2 * BUFBYTES];   // 40960 B
    const uint32_t sbase = smem_u32(smem);

    const int tid  = threadIdx.x;
    const int wid  = tid >> 5, lane = tid & 31;
    const int wr   = wid & 3;
    const int wc   = wid >> 2;
    const int row0 = blockIdx.y * 128;
    const int col0 = blockIdx.x * 128;

    const __nv_bfloat16* Aseg[3] = {A0, A1, A2};
    const __nv_bfloat16* Bseg[3] = {B0, B1, B2};

    float acc[2][8][4];
    #pragma unroll
    for (int i = 0; i < 2; ++i)
        #pragma unroll
        for (int j = 0; j < 8; ++j)
            #pragma unroll
            for (int k = 0; k < 4; ++k) acc[i][j][k] = 0.f;

    auto load_chunk = [&](int ch, int buf) {
        const int seg = ch >> 7, kc = ch & 127;
        const __nv_bfloat16* Ap = Aseg[seg] + (size_t)row0 * MATN + kc * 32;
        const __nv_bfloat16* Bp = Bseg[seg] + (size_t)col0 * MATN + kc * 32;
        const uint32_t sa = sbase + buf * BUFBYTES;
        const uint32_t sb = sa + ABYTES;
        #pragma unroll
        for (int p = 0; p < 2; ++p) {
            int q = tid + p * 256;
            int r = q >> 2, s = q & 3;
            cp16(sa + r * BROW + s * 16, Ap + (size_t)r * MATN + s * 8);
            cp16(sb + r * BROW + s * 16, Bp + (size_t)r * MATN + s * 8);
        }
        CP_COMMIT();
    };

    const int total = nseg * 128;
    load_chunk(0, 0);

    for (int ch = 0; ch < total; ++ch) {
        const int buf = ch & 1;
        if (ch + 1 < total) { load_chunk(ch + 1, buf ^ 1); CP_WAIT(1); }
        else                { CP_WAIT(0); }
        __syncthreads();

        const uint32_t sa = sbase + buf * BUFBYTES;
        const uint32_t sb = sa + ABYTES;
        #pragma unroll
        for (int kk = 0; kk < 2; ++kk) {
            uint32_t af[2][4], bf[4][4];
            #pragma unroll
            for (int mt = 0; mt < 2; ++mt) {
                uint32_t addr = sa + (uint32_t)(wr * 32 + mt * 16 + (lane & 15)) * BROW
                              + kk * 32 + (lane >> 4) * 16;
                LDSM_X4(af[mt], addr);
            }
            #pragma unroll
            for (int bp = 0; bp < 4; ++bp) {
                int grp = lane >> 3, wi = lane & 7;
                uint32_t addr = sb + (uint32_t)(wc * 64 + bp * 16 + wi + (grp >> 1) * 8) * BROW
                              + kk * 32 + (grp & 1) * 16;
                LDSM_X4(bf[bp], addr);
            }
            #pragma unroll
            for (int mt = 0; mt < 2; ++mt)
                #pragma unroll
                for (int nt = 0; nt < 8; ++nt)
                    mma_bf16(acc[mt][nt], af[mt], bf[nt >> 1][(nt & 1) * 2],
                             bf[nt >> 1][(nt & 1) * 2 + 1]);
        }
        __syncthreads();
    }

    #pragma unroll
    for (int mt = 0; mt < 2; ++mt) {
        #pragma unroll
        for (int half = 0; half < 2; ++half) {
            const int rg = row0 + wr * 32 + mt * 16 + (lane >> 2) + half * 8;
            const size_t rowbase = (size_t)rg * MATN;
            #pragma unroll
            for (int nt = 0; nt < 8; ++nt) {
                const int cc = col0 + wc * 64 + nt * 8 + (lane & 3) * 2;
                float v0 = acc[mt][nt][half * 2 + 0];
                float v1 = acc[mt][nt][half * 2 + 1];
                if (POLY) {
                    float2 e = *reinterpret_cast<const float2*>(E + rowbase + cc);
                    v0 = c2 * v0 + c1 * e.x + ((rg == cc)     ? c0 : 0.f);
                    v1 = c2 * v1 + c1 * e.y + ((rg == cc + 1) ? c0 : 0.f);
                }
                float2 o = make_float2(v0, v1);
                *reinterpret_cast<float2*>(C + rowbase + cc) = o;
            }
        }
    }
}

// ---------------- elementwise helpers ----------------
__global__ void k_sumsq(const float* __restrict__ x, int n, float* __restrict__ part) {
    __shared__ float sm[256];
    float acc = 0.f;
    for (int i = blockIdx.x * blockDim.x + threadIdx.x; i < n; i += gridDim.x * blockDim.x) {
        float v = x[i]; acc = fmaf(v, v, acc);
    }
    sm[threadIdx.x] = acc; __syncthreads();
    for (int s = 128; s > 0; s >>= 1) {
        if (threadIdx.x < s) sm[threadIdx.x] += sm[threadIdx.x + s];
        __syncthreads();
    }
    if (threadIdx.x == 0) part[blockIdx.x] = sm[0];
}
__global__ void k_finish(const float* __restrict__ part, float* __restrict__ dst) {
    __shared__ float sm[256];
    sm[threadIdx.x] = part[threadIdx.x]; __syncthreads();
    for (int s = 128; s > 0; s >>= 1) {
        if (threadIdx.x < s) sm[threadIdx.x] += sm[threadIdx.x + s];
        __syncthreads();
    }
    if (threadIdx.x == 0) *dst = sm[0];
}
__global__ void k_scalemat(const float* __restrict__ H, float* __restrict__ X,
                           const float* __restrict__ scal) {
    float s = rsqrtf(scal[0] + 1e-30f);
    for (size_t i = (size_t)blockIdx.x * blockDim.x + threadIdx.x; i < NSQL;
         i += (size_t)gridDim.x * blockDim.x)
        X[i] = H[i] * s;
}
// split X -> (hi, lo*sc) and transposed copies (hiT, loT*scT)
__global__ void k_splitT(const float* __restrict__ X,
                         __nv_bfloat16* __restrict__ hi, __nv_bfloat16* __restrict__ lo,
                         __nv_bfloat16* __restrict__ hiT, __nv_bfloat16* __restrict__ loT,
                         float sc, float scT) {
    __shared__ float t[32][33];
    int x0 = blockIdx.x * 32, y0 = blockIdx.y * 32;
    #pragma unroll
    for (int j = 0; j < 32; j += 8) {
        int r = y0 + threadIdx.y + j, c = x0 + threadIdx.x;
        float v = X[(size_t)r * MATN + c];
        t[threadIdx.y + j][threadIdx.x] = v;
        __nv_bfloat16 h = __float2bfloat16(v);
        hi[(size_t)r * MATN + c] = h;
        lo[(size_t)r * MATN + c] = __float2bfloat16((v - __bfloat162float(h)) * sc);
    }
    __syncthreads();
    #pragma unroll
    for (int j = 0; j < 32; j += 8) {
        int r = x0 + threadIdx.y + j, c = y0 + threadIdx.x;
        float v = t[threadIdx.x][threadIdx.y + j];
        __nv_bfloat16 h = __float2bfloat16(v);
        hiT[(size_t)r * MATN + c] = h;
        loT[(size_t)r * MATN + c] = __float2bfloat16((v - __bfloat162float(h)) * scT);
    }
}
__global__ void k_split(const float* __restrict__ M,
                        __nv_bfloat16* __restrict__ hi, __nv_bfloat16* __restrict__ lo,
                        float sc) {
    for (size_t i = (size_t)blockIdx.x * blockDim.x + threadIdx.x; i < NSQL;
         i += (size_t)gridDim.x * blockDim.x) {
        float v = M[i];
        __nv_bfloat16 h = __float2bfloat16(v);
        hi[i] = h;
        lo[i] = __float2bfloat16((v - __bfloat162float(h)) * sc);
    }
}
__global__ void k_sym(float* __restrict__ S) {
    __shared__ float ta[32][33], tb[32][33];
    int bi = blockIdx.y, bj = blockIdx.x;
    if (bj < bi) return;
    int i0 = bi * 32, j0 = bj * 32;
    #pragma unroll
    for (int j = 0; j < 32; j += 8) {
        ta[threadIdx.y + j][threadIdx.x] = S[(size_t)(i0 + threadIdx.y + j) * MATN + j0 + threadIdx.x];
        tb[threadIdx.y + j][threadIdx.x] = S[(size_t)(j0 + threadIdx.y + j) * MATN + i0 + threadIdx.x];
    }
    __syncthreads();
    #pragma unroll
    for (int j = 0; j < 32; j += 8) {
        float v = 0.5f * (ta[threadIdx.y + j][threadIdx.x] + tb[threadIdx.x][threadIdx.y + j]);
        S[(size_t)(i0 + threadIdx.y + j) * MATN + j0 + threadIdx.x] = v;
        float w = 0.5f * (tb[threadIdx.y + j][threadIdx.x] + ta[threadIdx.x][threadIdx.y + j]);
        S[(size_t)(j0 + threadIdx.y + j) * MATN + i0 + threadIdx.x] = w;
    }
}

// ---------------- driver ----------------
extern "C" void kernel_launch(void* const* d_in, const int* in_sizes, int n_in,
                              void* d_out, int out_size)
{
    const float* H = (const float*)d_in[0];
    float* out = (float*)d_out;

    float *X0, *X1, *S, *P, *part, *scal;
    __nv_bfloat16 *hA, *lA, *hAT, *lAT, *hS, *lS, *hP, *lP;
    cudaGetSymbolAddress((void**)&X0, g_X0);   cudaGetSymbolAddress((void**)&X1, g_X1);
    cudaGetSymbolAddress((void**)&S, g_S);     cudaGetSymbolAddress((void**)&P, g_P);
    cudaGetSymbolAddress((void**)&hA, g_hA);   cudaGetSymbolAddress((void**)&lA, g_lA);
    cudaGetSymbolAddress((void**)&hAT, g_hAT); cudaGetSymbolAddress((void**)&lAT, g_lAT);
    cudaGetSymbolAddress((void**)&hS, g_hS);   cudaGetSymbolAddress((void**)&lS, g_lS);
    cudaGetSymbolAddress((void**)&hP, g_hP);   cudaGetSymbolAddress((void**)&lP, g_lP);
    cudaGetSymbolAddress((void**)&part, g_part); cudaGetSymbolAddress((void**)&scal, g_scal);

    // X0 = H / ||H||_F
    k_sumsq<<<256, 256>>>(H, (int)NSQL, part);
    k_finish<<<1, 256>>>(part, scal);
    k_scalemat<<<2048, 256>>>(H, X0, scal);

    const int   NSTEP = 16;
    const float LA = 0.998f * 3.9337f, LB = 0.998f * -10.1084f, LC = 0.998f * 7.1747f;
    const float NA = 15.f / 8.f, NB = -10.f / 8.f, NC = 3.f / 8.f;

    dim3 grd(MATN / 128, MATN / 128);
    dim3 g32(MATN / 32, MATN / 32);
    dim3 b32(32, 8);
    float* Xc = X0;
    float* Xn = X1;

    for (int st = 0; st < NSTEP; ++st) {
        const float a = (st < 12) ? LA : NA;
        const float b = (st < 12) ? LB : NB;
        const float c = (st < 12) ? LC : NC;
        float* dst = (st == NSTEP - 1) ? out : Xn;

        // X split: plain lo for X*P; 2x lo on transposed copy for S cross-terms
        k_splitT<<<g32, b32>>>(Xc, hA, lA, hAT, lAT, 1.0f, 2.0f);

        // S = sym( hAT*hAT^T + hAT*(2 lAT)^T )  =  Xh^T Xh + Xh^T Xl + Xl^T Xh
        mma_gemm<0><<<grd, 256>>>(hAT, hAT, hAT, lAT, hAT, hAT, 2, S, nullptr, 0, 0, 0);
        k_sym<<<g32, b32>>>(S);
        k_split<<<2048, 256>>>(S, hS, lS, 2.0f);   // 2x lo for S^2 cross-terms

        // P = sym( c*(Sh*Sh + 2*Sh*Sl) + b*S + a*I )
        mma_gemm<1><<<grd, 256>>>(hS, hS, hS, lS, hS, hS, 2, P, S, a, b, c);
        k_sym<<<g32, b32>>>(P);
        k_split<<<2048, 256>>>(P, hP, lP, 1.0f);

        // X' = Xh*Ph + Xh*Pl + Xl*Ph   (P symmetric -> rows serve as columns)
        mma_gemm<0><<<grd, 256>>>(hA, hP, hA, lP, lA, hP, 3, dst, nullptr, 0, 0, 0);

        float* t = Xc; Xc = Xn; Xn = t;
    }
}

// round 6
// speedup vs baseline: 3.5564x; 1.3100x over previous
#include <cuda_runtime.h>
#include <cuda_bf16.h>
#include <cstdint>
#include <math.h>

#define MATN 4096
#define NSQL ((size_t)MATN * (size_t)MATN)

// ---------------- static device scratch ----------------
__device__ float g_X0[MATN * MATN];
__device__ float g_X1[MATN * MATN];
__device__ float g_S [MATN * MATN];
__device__ float g_P [MATN * MATN];
__device__ __nv_bfloat16 g_hA [MATN * MATN];
__device__ __nv_bfloat16 g_lA [MATN * MATN];
__device__ __nv_bfloat16 g_hAT[MATN * MATN];
__device__ __nv_bfloat16 g_lAT[MATN * MATN];
__device__ __nv_bfloat16 g_hS [MATN * MATN];
__device__ __nv_bfloat16 g_lS [MATN * MATN];
__device__ __nv_bfloat16 g_hP [MATN * MATN];
__device__ __nv_bfloat16 g_lP [MATN * MATN];
__device__ float g_v[MATN];
__device__ float g_y[MATN];
__device__ float g_part[256];
__device__ float g_scal[4];    // [1]=sigma_ray^2  [2]=tmp norm
__device__ int   g_flag;       // convergence detected (sticky within one launch)
__device__ int   g_flagL;      // latched at step start

// ---------------- helpers ----------------
__device__ __forceinline__ uint32_t smem_u32(const void* p) {
    uint32_t a;
    asm("{ .reg .u64 t; cvta.to.shared.u64 t, %1; cvt.u32.u64 %0, t; }" : "=r"(a) : "l"(p));
    return a;
}
__device__ __forceinline__ void cp16(uint32_t dst, const void* src) {
    asm volatile("cp.async.cg.shared.global [%0], [%1], 16;" :: "r"(dst), "l"(src));
}
#define CP_COMMIT() asm volatile("cp.async.commit_group;" ::: "memory")
#define CP_WAIT(N)  asm volatile("cp.async.wait_group %0;" :: "n"(N) : "memory")

#define LDSM_X4(r, a)                                                           \
    asm volatile("ldmatrix.sync.aligned.m8n8.x4.shared.b16 {%0,%1,%2,%3}, [%4];" \
        : "=r"((r)[0]), "=r"((r)[1]), "=r"((r)[2]), "=r"((r)[3]) : "r"(a))

__device__ __forceinline__ void mma_bf16(float* d, const uint32_t* a,
                                         uint32_t b0, uint32_t b1) {
    asm volatile(
        "mma.sync.aligned.m16n8k16.row.col.f32.bf16.bf16.f32 "
        "{%0,%1,%2,%3}, {%4,%5,%6,%7}, {%8,%9}, {%0,%1,%2,%3};"
        : "+f"(d[0]), "+f"(d[1]), "+f"(d[2]), "+f"(d[3])
        : "r"(a[0]), "r"(a[1]), "r"(a[2]), "r"(a[3]), "r"(b0), "r"(b1));
}

// ---------------- bf16 tensor-core GEMM (mma.sync) ----------------
// C = sum_s A_s * B_s^T ; POLY=1: C = c2*D + c1*E + c0*I.  Guarded by g_flagL.
#define BROW 80
#define ABYTES (128 * BROW)
#define BUFBYTES (2 * ABYTES)

template<int POLY>
__global__ void __launch_bounds__(256, 2)
mma_gemm(const __nv_bfloat16* __restrict__ A0, const __nv_bfloat16* __restrict__ B0,
         const __nv_bfloat16* __restrict__ A1, const __nv_bfloat16* __restrict__ B1,
         const __nv_bfloat16* __restrict__ A2, const __nv_bfloat16* __restrict__ B2,
         int nseg, float* __restrict__ C, const float* __restrict__ E,
         float c0, float c1, float c2)
{
    if (g_flagL) return;
    __shared__ __align__(16) char smem[2 * BUFBYTES];
    const uint32_t sbase = smem_u32(smem);

    const int tid  = threadIdx.x;
    const int wid  = tid >> 5, lane = tid & 31;
    const int wr   = wid & 3;
    const int wc   = wid >> 2;
    const int row0 = blockIdx.y * 128;
    const int col0 = blockIdx.x * 128;

    const __nv_bfloat16* Aseg[3] = {A0, A1, A2};
    const __nv_bfloat16* Bseg[3] = {B0, B1, B2};

    float acc[2][8][4];
    #pragma unroll
    for (int i = 0; i < 2; ++i)
        #pragma unroll
        for (int j = 0; j < 8; ++j)
            #pragma unroll
            for (int k = 0; k < 4; ++k) acc[i][j][k] = 0.f;

    auto load_chunk = [&](int ch, int buf) {
        const int seg = ch >> 7, kc = ch & 127;
        const __nv_bfloat16* Ap = Aseg[seg] + (size_t)row0 * MATN + kc * 32;
        const __nv_bfloat16* Bp = Bseg[seg] + (size_t)col0 * MATN + kc * 32;
        const uint32_t sa = sbase + buf * BUFBYTES;
        const uint32_t sb = sa + ABYTES;
        #pragma unroll
        for (int p = 0; p < 2; ++p) {
            int q = tid + p * 256;
            int r = q >> 2, s = q & 3;
            cp16(sa + r * BROW + s * 16, Ap + (size_t)r * MATN + s * 8);
            cp16(sb + r * BROW + s * 16, Bp + (size_t)r * MATN + s * 8);
        }
        CP_COMMIT();
    };

    const int total = nseg * 128;
    load_chunk(0, 0);

    for (int ch = 0; ch < total; ++ch) {
        const int buf = ch & 1;
        if (ch + 1 < total) { load_chunk(ch + 1, buf ^ 1); CP_WAIT(1); }
        else                { CP_WAIT(0); }
        __syncthreads();

        const uint32_t sa = sbase + buf * BUFBYTES;
        const uint32_t sb = sa + ABYTES;
        #pragma unroll
        for (int kk = 0; kk < 2; ++kk) {
            uint32_t af[2][4], bf[4][4];
            #pragma unroll
            for (int mt = 0; mt < 2; ++mt) {
                uint32_t addr = sa + (uint32_t)(wr * 32 + mt * 16 + (lane & 15)) * BROW
                              + kk * 32 + (lane >> 4) * 16;
                LDSM_X4(af[mt], addr);
            }
            #pragma unroll
            for (int bp = 0; bp < 4; ++bp) {
                int grp = lane >> 3, wi = lane & 7;
                uint32_t addr = sb + (uint32_t)(wc * 64 + bp * 16 + wi + (grp >> 1) * 8) * BROW
                              + kk * 32 + (grp & 1) * 16;
                LDSM_X4(bf[bp], addr);
            }
            #pragma unroll
            for (int mt = 0; mt < 2; ++mt)
                #pragma unroll
                for (int nt = 0; nt < 8; ++nt)
                    mma_bf16(acc[mt][nt], af[mt], bf[nt >> 1][(nt & 1) * 2],
                             bf[nt >> 1][(nt & 1) * 2 + 1]);
        }
        __syncthreads();
    }

    #pragma unroll
    for (int mt = 0; mt < 2; ++mt) {
        #pragma unroll
        for (int half = 0; half < 2; ++half) {
            const int rg = row0 + wr * 32 + mt * 16 + (lane >> 2) + half * 8;
            const size_t rowbase = (size_t)rg * MATN;
            #pragma unroll
            for (int nt = 0; nt < 8; ++nt) {
                const int cc = col0 + wc * 64 + nt * 8 + (lane & 3) * 2;
                float v0 = acc[mt][nt][half * 2 + 0];
                float v1 = acc[mt][nt][half * 2 + 1];
                if (POLY) {
                    float2 e = *reinterpret_cast<const float2*>(E + rowbase + cc);
                    v0 = c2 * v0 + c1 * e.x + ((rg == cc)     ? c0 : 0.f);
                    v1 = c2 * v1 + c1 * e.y + ((rg == cc + 1) ? c0 : 0.f);
                }
                float2 o = make_float2(v0, v1);
                *reinterpret_cast<float2*>(C + rowbase + cc) = o;
            }
        }
    }
}

// ---------------- small kernels ----------------
__global__ void k_reset() { g_flag = 0; g_flagL = 0; }
__global__ void k_latch() { g_flagL = g_flag; }

__global__ void k_copy_if(const float* __restrict__ src, float* __restrict__ dst) {
    if (!g_flagL) return;
    for (size_t i = (size_t)blockIdx.x * blockDim.x + threadIdx.x; i < NSQL / 4;
         i += (size_t)gridDim.x * blockDim.x)
        reinterpret_cast<float4*>(dst)[i] = reinterpret_cast<const float4*>(src)[i];
}

__global__ void k_sumsq(const float* __restrict__ x, int n, float* __restrict__ part) {
    __shared__ float sm[256];
    float acc = 0.f;
    for (int i = blockIdx.x * blockDim.x + threadIdx.x; i < n; i += gridDim.x * blockDim.x) {
        float v = x[i]; acc = fmaf(v, v, acc);
    }
    sm[threadIdx.x] = acc; __syncthreads();
    for (int s = 128; s > 0; s >>= 1) {
        if (threadIdx.x < s) sm[threadIdx.x] += sm[threadIdx.x + s];
        __syncthreads();
    }
    if (threadIdx.x == 0) part[blockIdx.x] = sm[0];
}
__global__ void k_finish(const float* __restrict__ part, float* __restrict__ dst) {
    __shared__ float sm[256];
    sm[threadIdx.x] = part[threadIdx.x]; __syncthreads();
    for (int s = 128; s > 0; s >>= 1) {
        if (threadIdx.x < s) sm[threadIdx.x] += sm[threadIdx.x + s];
        __syncthreads();
    }
    if (threadIdx.x == 0) *dst = sm[0];
}

__global__ void k_initv(float* v) {
    int j = blockIdx.x * blockDim.x + threadIdx.x;
    if (j < MATN) {
        unsigned h = (unsigned)j * 2654435761u;
        h ^= h >> 13; h *= 0x5bd1e995u; h ^= h >> 15;
        v[j] = ((float)(h & 0xFFFFu) / 65536.0f) - 0.5f + 0.001f;
    }
}
__global__ void k_normalize(float* v, const float* n2) {
    int j = blockIdx.x * blockDim.x + threadIdx.x;
    float s = rsqrtf(*n2 + 1e-30f);
    if (j < MATN) v[j] *= s;
}
// y = H v (one block of 128 per row)
__global__ void k_mvn(const float* __restrict__ H, const float* __restrict__ v,
                      float* __restrict__ y) {
    __shared__ float sm[128];
    int r = blockIdx.x;
    const float* row = H + (size_t)r * MATN;
    float acc = 0.f;
    for (int j = threadIdx.x; j < MATN; j += 128) acc = fmaf(row[j], v[j], acc);
    sm[threadIdx.x] = acc; __syncthreads();
    for (int s = 64; s > 0; s >>= 1) {
        if (threadIdx.x < s) sm[threadIdx.x] += sm[threadIdx.x + s];
        __syncthreads();
    }
    if (threadIdx.x == 0) y[r] = sm[0];
}
// z = H^T y : 128 blocks, 32 cols/block, 8 row-groups of 512
__global__ void k_mvt(const float* __restrict__ H, const float* __restrict__ y,
                      float* __restrict__ z) {
    __shared__ float sm[256];
    int tj = threadIdx.x & 31, gi = threadIdx.x >> 5;
    int j = blockIdx.x * 32 + tj;
    float acc = 0.f;
    for (int i = gi * 512; i < gi * 512 + 512; ++i)
        acc = fmaf(H[(size_t)i * MATN + j], y[i], acc);
    sm[threadIdx.x] = acc; __syncthreads();
    if (threadIdx.x < 32) {
        float t = 0.f;
        #pragma unroll
        for (int g = 0; g < 8; ++g) t += sm[threadIdx.x + 32 * g];
        z[j] = t;
    }
}

// split X -> (hi, lo) and transposed copies; optional prescale from g_scal[1]
__global__ void k_splitT(const float* __restrict__ X,
                         __nv_bfloat16* __restrict__ hi, __nv_bfloat16* __restrict__ lo,
                         __nv_bfloat16* __restrict__ hiT, __nv_bfloat16* __restrict__ loT,
                         float scT, int prescale) {
    if (g_flagL) return;
    __shared__ float t[32][33];
    float s = prescale ? (rsqrtf(g_scal[1] + 1e-30f) / 1.10f) : 1.0f;
    int x0 = blockIdx.x * 32, y0 = blockIdx.y * 32;
    #pragma unroll
    for (int j = 0; j < 32; j += 8) {
        int r = y0 + threadIdx.y + j, c = x0 + threadIdx.x;
        float v = X[(size_t)r * MATN + c] * s;
        t[threadIdx.y + j][threadIdx.x] = v;
        __nv_bfloat16 h = __float2bfloat16(v);
        hi[(size_t)r * MATN + c] = h;
        lo[(size_t)r * MATN + c] = __float2bfloat16(v - __bfloat162float(h));
    }
    __syncthreads();
    #pragma unroll
    for (int j = 0; j < 32; j += 8) {
        int r = x0 + threadIdx.y + j, c = y0 + threadIdx.x;
        float v = t[threadIdx.x][threadIdx.y + j];
        __nv_bfloat16 h = __float2bfloat16(v);
        hiT[(size_t)r * MATN + c] = h;
        loT[(size_t)r * MATN + c] = __float2bfloat16((v - __bfloat162float(h)) * scT);
    }
}

// S <- (S+S^T)/2 and split into hi + lo*sc (both mirror tiles)
__global__ void k_symsplit(float* __restrict__ S,
                           __nv_bfloat16* __restrict__ hi, __nv_bfloat16* __restrict__ lo,
                           float sc) {
    if (g_flagL) return;
    __shared__ float ta[32][33], tb[32][33];
    int bi = blockIdx.y, bj = blockIdx.x;
    if (bj < bi) return;
    int i0 = bi * 32, j0 = bj * 32;
    #pragma unroll
    for (int j = 0; j < 32; j += 8) {
        ta[threadIdx.y + j][threadIdx.x] = S[(size_t)(i0 + threadIdx.y + j) * MATN + j0 + threadIdx.x];
        tb[threadIdx.y + j][threadIdx.x] = S[(size_t)(j0 + threadIdx.y + j) * MATN + i0 + threadIdx.x];
    }
    __syncthreads();
    #pragma unroll
    for (int j = 0; j < 32; j += 8) {
        size_t idx1 = (size_t)(i0 + threadIdx.y + j) * MATN + j0 + threadIdx.x;
        float v = 0.5f * (ta[threadIdx.y + j][threadIdx.x] + tb[threadIdx.x][threadIdx.y + j]);
        S[idx1] = v;
        __nv_bfloat16 h = __float2bfloat16(v);
        hi[idx1] = h;
        lo[idx1] = __float2bfloat16((v - __bfloat162float(h)) * sc);

        size_t idx2 = (size_t)(j0 + threadIdx.y + j) * MATN + i0 + threadIdx.x;
        float w = 0.5f * (tb[threadIdx.y + j][threadIdx.x] + ta[threadIdx.x][threadIdx.y + j]);
        S[idx2] = w;
        __nv_bfloat16 h2 = __float2bfloat16(w);
        hi[idx2] = h2;
        lo[idx2] = __float2bfloat16((w - __bfloat162float(h2)) * sc);
    }
}

// residual R^2 = || S - I ||_F^2
__global__ void k_resid(const float* __restrict__ S, float* __restrict__ part) {
    if (g_flagL) { if (blockIdx.x == 0 && threadIdx.x == 0) {} }
    __shared__ float sm[256];
    float acc = 0.f;
    if (!g_flagL) {
        for (size_t i = (size_t)blockIdx.x * blockDim.x + threadIdx.x; i < NSQL;
             i += (size_t)gridDim.x * blockDim.x) {
            float d = S[i] - ((i / MATN == i % MATN) ? 1.f : 0.f);
            acc = fmaf(d, d, acc);
        }
    }
    sm[threadIdx.x] = acc; __syncthreads();
    for (int s = 128; s > 0; s >>= 1) {
        if (threadIdx.x < s) sm[threadIdx.x] += sm[threadIdx.x + s];
        __syncthreads();
    }
    if (threadIdx.x == 0) part[blockIdx.x] = sm[0];
}
__global__ void k_detect(const float* __restrict__ part) {
    if (g_flagL) return;
    __shared__ float sm[256];
    sm[threadIdx.x] = part[threadIdx.x]; __syncthreads();
    for (int s = 128; s > 0; s >>= 1) {
        if (threadIdx.x < s) sm[threadIdx.x] += sm[threadIdx.x + s];
        __syncthreads();
    }
    if (threadIdx.x == 0 && sm[0] < 0.01f) g_flag = 1;
}

// ---------------- driver ----------------
extern "C" void kernel_launch(void* const* d_in, const int* in_sizes, int n_in,
                              void* d_out, int out_size)
{
    const float* H = (const float*)d_in[0];
    float* out = (float*)d_out;

    float *X0, *X1, *S, *P, *v, *y, *part, *scal;
    __nv_bfloat16 *hA, *lA, *hAT, *lAT, *hS, *lS, *hP, *lP;
    cudaGetSymbolAddress((void**)&X0, g_X0);   cudaGetSymbolAddress((void**)&X1, g_X1);
    cudaGetSymbolAddress((void**)&S, g_S);     cudaGetSymbolAddress((void**)&P, g_P);
    cudaGetSymbolAddress((void**)&hA, g_hA);   cudaGetSymbolAddress((void**)&lA, g_lA);
    cudaGetSymbolAddress((void**)&hAT, g_hAT); cudaGetSymbolAddress((void**)&lAT, g_lAT);
    cudaGetSymbolAddress((void**)&hS, g_hS);   cudaGetSymbolAddress((void**)&lS, g_lS);
    cudaGetSymbolAddress((void**)&hP, g_hP);   cudaGetSymbolAddress((void**)&lP, g_lP);
    cudaGetSymbolAddress((void**)&v, g_v);     cudaGetSymbolAddress((void**)&y, g_y);
    cudaGetSymbolAddress((void**)&part, g_part); cudaGetSymbolAddress((void**)&scal, g_scal);

    k_reset<<<1, 1>>>();

    // --- spectral norm estimate: 10 power iterations, Rayleigh lower bound ---
    k_initv<<<(MATN + 255) / 256, 256>>>(v);
    for (int t = 0; t < 10; ++t) {
        k_sumsq<<<256, 256>>>(v, MATN, part);
        k_finish<<<1, 256>>>(part, scal + 2);
        k_normalize<<<(MATN + 255) / 256, 256>>>(v, scal + 2);
        k_mvn<<<MATN, 128>>>(H, v, y);
        k_mvt<<<MATN / 32, 256>>>(H, y, v);
    }
    k_sumsq<<<256, 256>>>(v, MATN, part);
    k_finish<<<1, 256>>>(part, scal + 2);
    k_normalize<<<(MATN + 255) / 256, 256>>>(v, scal + 2);
    k_mvn<<<MATN, 128>>>(H, v, y);
    k_sumsq<<<256, 256>>>(y, MATN, part);
    k_finish<<<1, 256>>>(part, scal + 1);   // scal[1] = sigma_ray^2

    // --- schedule: 1 x L125, 8 x LA, 1 x COMP, 2 x NS  (12 steps) ---
    const int NSTEP = 12;
    float ca[NSTEP], cb[NSTEP], cc[NSTEP];
    for (int i = 0; i < NSTEP; ++i) {
        if (i == 0)      { ca[i] = 3.140664f;  cb[i] = -5.165150f;  cc[i] = 2.346307f; }
        else if (i <= 8) { ca[i] = 3.9258326f; cb[i] = -10.0881832f; cc[i] = 7.1603506f; }
        else if (i == 9) { ca[i] = 2.8426f;    cb[i] = -4.4442f;    cc[i] = 2.6015f; }
        else             { ca[i] = 1.875f;     cb[i] = -1.25f;      cc[i] = 0.375f; }
    }

    dim3 grd(MATN / 128, MATN / 128);
    dim3 g32(MATN / 32, MATN / 32);
    dim3 b32(32, 8);
    float* Xc = X0;
    float* Xn = X1;

    for (int st = 0; st < NSTEP; ++st) {
        float* dst = (st == NSTEP - 1) ? out : Xn;
        const float a = ca[st], b = cb[st], c = cc[st];

        k_latch<<<1, 1>>>();
        k_copy_if<<<1024, 256>>>((st == 0) ? X0 : Xc, dst);  // only runs when converged

        // split X (step 0 reads H via prescale; Xc == X0 alias unused then)
        k_splitT<<<g32, b32>>>((st == 0) ? H : Xc, hA, lA, hAT, lAT, 2.0f, (st == 0) ? 1 : 0);

        // S = sym( hAT*hAT^T + hAT*(2 lAT)^T )
        mma_gemm<0><<<grd, 256>>>(hAT, hAT, hAT, lAT, hAT, hAT, 2, S, nullptr, 0, 0, 0);
        k_symsplit<<<g32, b32>>>(S, hS, lS, 2.0f);

        // convergence check on S (sets flag for NEXT steps)
        k_resid<<<256, 256>>>(S, part);
        k_detect<<<1, 256>>>(part);

        // P = sym( c*(Sh*Sh + 2*Sh*Sl) + b*S + a*I )
        mma_gemm<1><<<grd, 256>>>(hS, hS, hS, lS, hS, hS, 2, P, S, a, b, c);
        k_symsplit<<<g32, b32>>>(P, hP, lP, 1.0f);

        // X' = Xh*Ph + Xh*Pl + Xl*Ph
        mma_gemm<0><<<grd, 256>>>(hA, hP, hA, lP, lA, hP, 3, dst, nullptr, 0, 0, 0);

        float* t = Xc; Xc = Xn; Xn = t;
        if (st == 0) Xc = X1;   // step 0 wrote X1 (dst), X0 never materialized
    }
}